// round 4
// baseline (speedup 1.0000x reference)
#include <cuda_runtime.h>

// YOLO decode, 3 scales fused.
// Scales 26/52 (HW divisible by 4): 1 thread = 4 consecutive cells, 15 LDG.128,
// stage 60 contiguous floats in smem, block-coalesced float4 store.
// Scale 13 (HW=169, odd): scalar 1-cell-per-thread path (4.8% of work).

#define TPB 128

__global__ __launch_bounds__(TPB) void detector_decode_kernel(
    const float* __restrict__ in13,
    const float* __restrict__ in26,
    const float* __restrict__ in52,
    const float* __restrict__ pthresh,
    float* __restrict__ out)
{
    __shared__ float s[TPB * 4 * 15];   // 30720 B

    const int HW13 = 169, HW26 = 676, HW52 = 2704;
    const int N13 = 32 * HW13;   // 5408
    const int N26 = 32 * HW26;   // 21632
    const int N52 = 32 * HW52;   // 86528
    const int B13 = (N13 + TPB - 1) / TPB;            // 43 (scalar, 128 cells/blk)
    const int B26 = (N26 / 4 + TPB - 1) / TPB;        // 43 (vec, 512 cells/blk)

    const int blk = blockIdx.x;
    const int tid = threadIdx.x;
    const float thresh = __ldg(pthresh);

    int cellBase, nvalid;
    long outBase;

    if (blk < B13) {
        // ---------- scale 13, scalar path ----------
        const int HW = HW13, W = 13;
        const float t = 32.0f;
        cellBase = blk * TPB;
        outBase = 0;
        nvalid = min(TPB, N13 - cellBase);
        const int c = cellBase + tid;
        if (c < N13) {
            const int b  = c / HW;
            const int hw = c - b * HW;
            const int h  = hw / W;
            const int w  = hw - h * W;
            const float* __restrict__ base = in13 + (long)b * 255 * HW + hw;
            const float aws[3] = {116.0f, 156.0f, 373.0f};
            const float ahs[3] = {90.0f, 198.0f, 326.0f};

            float cf[3], xv[3], yv[3], wv[3], hv[3];
            #pragma unroll
            for (int a = 0; a < 3; ++a) {
                const float* __restrict__ p = base + (long)(a * 85) * HW;
                cf[a] = p[0]; xv[a] = p[HW]; yv[a] = p[2*HW];
                wv[a] = p[3*HW]; hv[a] = p[4*HW];
            }
            float* __restrict__ so = s + tid * 15;
            #pragma unroll
            for (int a = 0; a < 3; ++a) {
                const bool m = cf[a] > thresh;
                so[a*5+0] = m ? (float)b : 0.0f;
                so[a*5+1] = m ? ((float)w + xv[a]) * t : 0.0f;
                so[a*5+2] = m ? ((float)h + yv[a]) * t : 0.0f;
                so[a*5+3] = m ? aws[a] * __expf(wv[a]) : 0.0f;
                so[a*5+4] = m ? ahs[a] * __expf(hv[a]) : 0.0f;
            }
        }
    } else {
        // ---------- scales 26 / 52, vectorized path ----------
        const float* __restrict__ in;
        int HW, W, N, voff;
        float t, aws0, aws1, aws2, ahs0, ahs1, ahs2;
        if (blk < B13 + B26) {
            in = in26; HW = HW26; W = 26; N = N26; t = 16.0f;
            voff = (blk - B13) * TPB;
            outBase = (long)N13 * 15;
            aws0 = 30.0f; aws1 = 62.0f; aws2 = 59.0f;
            ahs0 = 61.0f; ahs1 = 45.0f; ahs2 = 119.0f;
        } else {
            in = in52; HW = HW52; W = 52; N = N52; t = 8.0f;
            voff = (blk - B13 - B26) * TPB;
            outBase = (long)(N13 + N26) * 15;
            aws0 = 10.0f; aws1 = 16.0f; aws2 = 33.0f;
            ahs0 = 13.0f; ahs1 = 30.0f; ahs2 = 23.0f;
        }
        cellBase = voff * 4;
        nvalid = min(TPB * 4, N - cellBase);

        const int c0 = (voff + tid) * 4;
        if (c0 < N) {
            const int b   = c0 / HW;            // group never crosses batch (HW%4==0)
            const int hw0 = c0 - b * HW;
            const float* __restrict__ base = in + (long)b * 255 * HW + hw0;

            // 15 independent LDG.128s.
            float4 cf[3], xv[3], yv[3], wv[3], hv[3];
            #pragma unroll
            for (int a = 0; a < 3; ++a) {
                const float* __restrict__ p = base + (long)(a * 85) * HW;
                cf[a] = *(const float4*)(p);
                xv[a] = *(const float4*)(p + HW);
                yv[a] = *(const float4*)(p + 2*HW);
                wv[a] = *(const float4*)(p + 3*HW);
                hv[a] = *(const float4*)(p + 4*HW);
            }

            const float aw[3] = {aws0, aws1, aws2};
            const float ah[3] = {ahs0, ahs1, ahs2};
            const float fb = (float)b;
            float* __restrict__ so = s + tid * 60;

            #pragma unroll
            for (int j = 0; j < 4; ++j) {
                const int hw = hw0 + j;
                const int h  = hw / W;
                const int w  = hw - h * W;
                const float fw = (float)w, fh = (float)h;
                #pragma unroll
                for (int a = 0; a < 3; ++a) {
                    const float cc = ((const float*)&cf[a])[j];
                    const bool m = cc > thresh;
                    float* __restrict__ q = so + j * 15 + a * 5;
                    q[0] = m ? fb : 0.0f;
                    q[1] = m ? (fw + ((const float*)&xv[a])[j]) * t : 0.0f;
                    q[2] = m ? (fh + ((const float*)&yv[a])[j]) * t : 0.0f;
                    q[3] = m ? aw[a] * __expf(((const float*)&wv[a])[j]) : 0.0f;
                    q[4] = m ? ah[a] * __expf(((const float*)&hv[a])[j]) : 0.0f;
                }
            }
        }
    }

    __syncthreads();

    // Coalesced block store. nvalid is always a multiple of 32 cells
    // -> totFloats multiple of 4; outBase and cellBase*15 multiples of 4.
    const int totFloats = nvalid * 15;
    float* __restrict__ dst = out + outBase + (long)cellBase * 15;
    float4* __restrict__ d4 = (float4*)dst;
    const float4* __restrict__ s4 = (const float4*)s;
    const int n4 = totFloats >> 2;
    for (int i = tid; i < n4; i += TPB) d4[i] = s4[i];
}

extern "C" void kernel_launch(void* const* d_in, const int* in_sizes, int n_in,
                              void* d_out, int out_size)
{
    const float* in13 = (const float*)d_in[0];
    const float* in26 = (const float*)d_in[1];
    const float* in52 = (const float*)d_in[2];
    const float* pthresh = (const float*)d_in[3];
    float* out = (float*)d_out;

    const int N13 = 32 * 169, N26 = 32 * 676, N52 = 32 * 2704;
    const int B13 = (N13 + TPB - 1) / TPB;            // 43
    const int B26 = (N26 / 4 + TPB - 1) / TPB;        // 43
    const int B52 = (N52 / 4 + TPB - 1) / TPB;        // 169
    detector_decode_kernel<<<B13 + B26 + B52, TPB>>>(in13, in26, in52, pthresh, out);
}

// round 5
// speedup vs baseline: 1.1061x; 1.1061x over previous
#include <cuda_runtime.h>

// YOLO decode, 3 scales fused. 1 thread = 1 cell (15 coalesced scalar loads),
// per-WARP smem staging (no block barrier): each warp stages its 32 cells'
// 480 contiguous output floats and copies them out as 120 float4s, retiring
// independently of other warps.

#define TPB 256

__global__ __launch_bounds__(TPB) void detector_decode_kernel(
    const float* __restrict__ in13,
    const float* __restrict__ in26,
    const float* __restrict__ in52,
    const float* __restrict__ pthresh,
    float* __restrict__ out)
{
    __shared__ float s[TPB * 15];

    const int HW13 = 169, HW26 = 676, HW52 = 2704;
    const int N13 = 32 * HW13;   // 5408
    const int N26 = 32 * HW26;   // 21632
    const int N52 = 32 * HW52;   // 86528
    const int B13 = (N13 + TPB - 1) / TPB;   // 22
    const int B26 = (N26 + TPB - 1) / TPB;   // 85

    const int blk = blockIdx.x;
    const int tid = threadIdx.x;
    const int warp = tid >> 5;
    const int lane = tid & 31;

    const float* __restrict__ in;
    int HW, W, N, cellBase, outBase;   // all fit in int32
    float t;
    float aw0, aw1, aw2, ah0, ah1, ah2;

    if (blk < B13) {
        in = in13; HW = HW13; W = 13; t = 32.0f; N = N13;
        cellBase = blk * TPB; outBase = 0;
        aw0 = 116.0f; aw1 = 156.0f; aw2 = 373.0f;
        ah0 =  90.0f; ah1 = 198.0f; ah2 = 326.0f;
    } else if (blk < B13 + B26) {
        in = in26; HW = HW26; W = 26; t = 16.0f; N = N26;
        cellBase = (blk - B13) * TPB; outBase = N13 * 15;
        aw0 = 30.0f; aw1 = 62.0f; aw2 = 59.0f;
        ah0 = 61.0f; ah1 = 45.0f; ah2 = 119.0f;
    } else {
        in = in52; HW = HW52; W = 52; t = 8.0f; N = N52;
        cellBase = (blk - B13 - B26) * TPB; outBase = (N13 + N26) * 15;
        aw0 = 10.0f; aw1 = 16.0f; aw2 = 33.0f;
        ah0 = 13.0f; ah1 = 30.0f; ah2 = 23.0f;
    }

    const float thresh = __ldg(pthresh);
    const int c = cellBase + tid;

    if (c < N) {
        const int b  = c / HW;
        const int hw = c - b * HW;
        const int h  = hw / W;
        const int w  = hw - h * W;

        // (b, ch, h, w) -> b*255*HW + ch*HW + hw   (int32 throughout)
        const float* __restrict__ base = in + b * 255 * HW + hw;
        const float* __restrict__ p0 = base;
        const float* __restrict__ p1 = base + 85  * HW;
        const float* __restrict__ p2 = base + 170 * HW;

        // Front-batch all 15 independent loads.
        const float c0 = p0[0];
        const float x0 = p0[HW], y0 = p0[2*HW], w0 = p0[3*HW], h0 = p0[4*HW];
        const float c1 = p1[0];
        const float x1 = p1[HW], y1 = p1[2*HW], w1 = p1[3*HW], h1 = p1[4*HW];
        const float c2 = p2[0];
        const float x2 = p2[HW], y2 = p2[2*HW], w2 = p2[3*HW], h2 = p2[4*HW];

        const float fb = (float)b;
        const float fw = (float)w;
        const float fh = (float)h;

        float* __restrict__ so = s + tid * 15;

        const bool m0 = c0 > thresh;
        so[0]  = m0 ? fb : 0.0f;
        so[1]  = m0 ? (fw + x0) * t : 0.0f;
        so[2]  = m0 ? (fh + y0) * t : 0.0f;
        so[3]  = m0 ? aw0 * __expf(w0) : 0.0f;
        so[4]  = m0 ? ah0 * __expf(h0) : 0.0f;

        const bool m1 = c1 > thresh;
        so[5]  = m1 ? fb : 0.0f;
        so[6]  = m1 ? (fw + x1) * t : 0.0f;
        so[7]  = m1 ? (fh + y1) * t : 0.0f;
        so[8]  = m1 ? aw1 * __expf(w1) : 0.0f;
        so[9]  = m1 ? ah1 * __expf(h1) : 0.0f;

        const bool m2 = c2 > thresh;
        so[10] = m2 ? fb : 0.0f;
        so[11] = m2 ? (fw + x2) * t : 0.0f;
        so[12] = m2 ? (fh + y2) * t : 0.0f;
        so[13] = m2 ? aw2 * __expf(w2) : 0.0f;
        so[14] = m2 ? ah2 * __expf(h2) : 0.0f;
    }

    __syncwarp();

    // Per-warp coalesced copy-out: warp's 32 cells -> 480 contiguous floats.
    // warpCell is a multiple of 32 -> byte offset multiple of 1920 -> 16B aligned.
    const int warpCell = cellBase + warp * 32;
    if (warpCell < N) {
        const float4* __restrict__ s4 = (const float4*)(s + warp * 480);
        float4* __restrict__ d4 = (float4*)(out + outBase + warpCell * 15);
        #pragma unroll
        for (int i = 0; i < 4; ++i) {
            const int idx = lane + i * 32;
            if (idx < 120) d4[idx] = s4[idx];
        }
    }
}

extern "C" void kernel_launch(void* const* d_in, const int* in_sizes, int n_in,
                              void* d_out, int out_size)
{
    const float* in13 = (const float*)d_in[0];
    const float* in26 = (const float*)d_in[1];
    const float* in52 = (const float*)d_in[2];
    const float* pthresh = (const float*)d_in[3];
    float* out = (float*)d_out;

    const int N13 = 32 * 169, N26 = 32 * 676, N52 = 32 * 2704;
    const int B13 = (N13 + TPB - 1) / TPB;   // 22
    const int B26 = (N26 + TPB - 1) / TPB;   // 85
    const int B52 = (N52 + TPB - 1) / TPB;   // 338
    detector_decode_kernel<<<B13 + B26 + B52, TPB>>>(in13, in26, in52, pthresh, out);
}

// round 6
// speedup vs baseline: 1.3029x; 1.1779x over previous
#include <cuda_runtime.h>

// YOLO decode, 3 scales fused, each scale a fully compile-time-specialized
// template path (constexpr HW/W/stride/anchors -> magic-number division,
// immediate-operand FFMA). 1 thread = 1 cell, 15 front-batched coalesced
// loads, smem staging, per-warp coalesced float4 copy-out.

#define TPB 256

template<int HW, int W, int TT,
         int AW0, int AH0, int AW1, int AH1, int AW2, int AH2>
__device__ __forceinline__ void decode_scale(const float* __restrict__ in,
                                             float* __restrict__ s,
                                             int cellBase, int N,
                                             float thresh, int tid)
{
    const int c = cellBase + tid;
    if (c >= N) return;

    const int b  = c / HW;            // constexpr HW -> mul+shift
    const int hw = c - b * HW;
    const int h  = hw / W;            // constexpr W  -> mul+shift
    const int w  = hw - h * W;

    const float* __restrict__ base = in + b * (255 * HW) + hw;
    const float* __restrict__ p0 = base;
    const float* __restrict__ p1 = base + 85  * HW;
    const float* __restrict__ p2 = base + 170 * HW;

    // 15 independent coalesced loads in flight.
    const float c0 = p0[0];
    const float x0 = p0[HW], y0 = p0[2*HW], w0 = p0[3*HW], h0 = p0[4*HW];
    const float c1 = p1[0];
    const float x1 = p1[HW], y1 = p1[2*HW], w1 = p1[3*HW], h1 = p1[4*HW];
    const float c2 = p2[0];
    const float x2 = p2[HW], y2 = p2[2*HW], w2 = p2[3*HW], h2 = p2[4*HW];

    const float fb = (float)b;
    const float fw = (float)w;
    const float fh = (float)h;
    const float t = (float)TT;

    float* __restrict__ so = s + tid * 15;

    const bool m0 = c0 > thresh;
    so[0]  = m0 ? fb : 0.0f;
    so[1]  = m0 ? (fw + x0) * t : 0.0f;
    so[2]  = m0 ? (fh + y0) * t : 0.0f;
    so[3]  = m0 ? (float)AW0 * __expf(w0) : 0.0f;
    so[4]  = m0 ? (float)AH0 * __expf(h0) : 0.0f;

    const bool m1 = c1 > thresh;
    so[5]  = m1 ? fb : 0.0f;
    so[6]  = m1 ? (fw + x1) * t : 0.0f;
    so[7]  = m1 ? (fh + y1) * t : 0.0f;
    so[8]  = m1 ? (float)AW1 * __expf(w1) : 0.0f;
    so[9]  = m1 ? (float)AH1 * __expf(h1) : 0.0f;

    const bool m2 = c2 > thresh;
    so[10] = m2 ? fb : 0.0f;
    so[11] = m2 ? (fw + x2) * t : 0.0f;
    so[12] = m2 ? (fh + y2) * t : 0.0f;
    so[13] = m2 ? (float)AW2 * __expf(w2) : 0.0f;
    so[14] = m2 ? (float)AH2 * __expf(h2) : 0.0f;
}

__global__ __launch_bounds__(TPB) void detector_decode_kernel(
    const float* __restrict__ in13,
    const float* __restrict__ in26,
    const float* __restrict__ in52,
    const float* __restrict__ pthresh,
    float* __restrict__ out)
{
    __shared__ float s[TPB * 15];

    constexpr int HW13 = 169, HW26 = 676, HW52 = 2704;
    constexpr int N13 = 32 * HW13;   // 5408
    constexpr int N26 = 32 * HW26;   // 21632
    constexpr int N52 = 32 * HW52;   // 86528
    constexpr int B13 = (N13 + TPB - 1) / TPB;   // 22
    constexpr int B26 = (N26 + TPB - 1) / TPB;   // 85

    const float thresh = __ldg(pthresh);   // issued first; latency overlaps setup

    const int blk = blockIdx.x;
    const int tid = threadIdx.x;
    const int warp = tid >> 5;
    const int lane = tid & 31;

    int cellBase, N, outBase;

    if (blk < B13) {
        N = N13; cellBase = blk * TPB; outBase = 0;
        decode_scale<HW13, 13, 32, 116, 90, 156, 198, 373, 326>(
            in13, s, cellBase, N, thresh, tid);
    } else if (blk < B13 + B26) {
        N = N26; cellBase = (blk - B13) * TPB; outBase = N13 * 15;
        decode_scale<HW26, 26, 16, 30, 61, 62, 45, 59, 119>(
            in26, s, cellBase, N, thresh, tid);
    } else {
        N = N52; cellBase = (blk - B13 - B26) * TPB; outBase = (N13 + N26) * 15;
        decode_scale<HW52, 52, 8, 10, 13, 16, 30, 33, 23>(
            in52, s, cellBase, N, thresh, tid);
    }

    __syncwarp();

    // Per-warp coalesced copy-out: this warp's 32 cells -> 480 contiguous floats.
    // warpCell multiple of 32 -> gmem offset multiple of 480 floats (16B aligned).
    const int warpCell = cellBase + warp * 32;
    if (warpCell < N) {
        const float4* __restrict__ s4 = (const float4*)(s + warp * 480);
        float4* __restrict__ d4 = (float4*)(out + outBase + warpCell * 15);
        #pragma unroll
        for (int i = 0; i < 4; ++i) {
            const int idx = lane + i * 32;
            if (idx < 120) d4[idx] = s4[idx];
        }
    }
}

extern "C" void kernel_launch(void* const* d_in, const int* in_sizes, int n_in,
                              void* d_out, int out_size)
{
    const float* in13 = (const float*)d_in[0];
    const float* in26 = (const float*)d_in[1];
    const float* in52 = (const float*)d_in[2];
    const float* pthresh = (const float*)d_in[3];
    float* out = (float*)d_out;

    constexpr int N13 = 32 * 169, N26 = 32 * 676, N52 = 32 * 2704;
    constexpr int B13 = (N13 + TPB - 1) / TPB;   // 22
    constexpr int B26 = (N26 + TPB - 1) / TPB;   // 85
    constexpr int B52 = (N52 + TPB - 1) / TPB;   // 338
    detector_decode_kernel<<<B13 + B26 + B52, TPB>>>(in13, in26, in52, pthresh, out);
}